// round 1
// baseline (speedup 1.0000x reference)
#include <cuda_runtime.h>

#define BATCH 4
#define CH    128
#define CIN   256
#define HH    224
#define WW    224
#define HW    50176
#define NCLS  41
#define KTOT  2304   // 256 * 9

// ---------------- scratch (static device globals; no allocs) ----------------
static __device__ float g_xcat[(size_t)BATCH * CIN * HW];  // [b][ci][p] concat(add,mul)
static __device__ float g_fuse[(size_t)BATCH * CH * HW];   // conv output
static __device__ float g_wT[KTOT * CH];                   // transposed weights [k][oc]
static __device__ float g_sum_d[BATCH * NCLS * CH];
static __device__ float g_sum_f[BATCH * NCLS * CH];
static __device__ float g_cnt[BATCH * NCLS];
static __device__ float g_scale[2 * BATCH * CH];           // [which(0=d,1=f)][b][c]

__device__ __forceinline__ float sigmoid_fast(float x) {
    return 1.f / (1.f + __expf(-x));
}

// ---------------- prep: add / mul into concat buffer (float4) ----------------
__global__ void prep_kernel(const float* __restrict__ r, const float* __restrict__ dd) {
    int idx = blockIdx.x * 256 + threadIdx.x;
    const int n4 = BATCH * CH * HW / 4;
    if (idx >= n4) return;
    int i = idx * 4;
    int b = i / (CH * HW);
    int rem = i - b * (CH * HW);
    float4 rv = *reinterpret_cast<const float4*>(r + i);
    float4 dv = *reinterpret_cast<const float4*>(dd + i);
    float4 add, mul;
    add.x = rv.x + dv.x; add.y = rv.y + dv.y; add.z = rv.z + dv.z; add.w = rv.w + dv.w;
    mul.x = rv.x * sigmoid_fast(dv.x);
    mul.y = rv.y * sigmoid_fast(dv.y);
    mul.z = rv.z * sigmoid_fast(dv.z);
    mul.w = rv.w * sigmoid_fast(dv.w);
    float* base = g_xcat + (size_t)b * CIN * HW;
    *reinterpret_cast<float4*>(base + rem) = add;
    *reinterpret_cast<float4*>(base + (size_t)CH * HW + rem) = mul;
}

// ---------------- weight transpose: w[oc][k] -> wT[k][oc] ----------------
__global__ void wtrans_kernel(const float* __restrict__ w) {
    int i = blockIdx.x * 256 + threadIdx.x;
    if (i >= KTOT * CH) return;
    int oc = i & (CH - 1);
    int k  = i >> 7;
    g_wT[i] = w[(size_t)oc * KTOT + k];
}

// ---------------- zero accumulators (must run every launch) ----------------
__global__ void zero_kernel() {
    int i = blockIdx.x * 256 + threadIdx.x;
    if (i < BATCH * NCLS * CH) { g_sum_d[i] = 0.f; g_sum_f[i] = 0.f; }
    if (i < BATCH * NCLS) g_cnt[i] = 0.f;
}

// ---------------- RA segment stats (shared-memory privatized bins) ----------------
// mode 0: feats = dfeats (d tensor), sums = g_sum_d, also counts
// mode 1: feats = g_fuse,            sums = g_sum_f
__global__ void ra_stats_kernel(const float* __restrict__ dfeats,
                                const int* __restrict__ label, int mode) {
    __shared__ float bins[NCLS * 129];   // pad 129: bank = (lab + c) % 32
    __shared__ float cnts[NCLS];
    __shared__ int   slab[1024];

    const float* feats = mode ? g_fuse : dfeats;
    float* sums = mode ? g_sum_f : g_sum_d;

    const int b   = blockIdx.y;
    const int p0  = blockIdx.x * 1024;
    const int tid = threadIdx.x;

    for (int i = tid; i < NCLS * 129; i += 256) bins[i] = 0.f;
    if (tid < NCLS) cnts[tid] = 0.f;
    for (int i = tid; i < 1024; i += 256) {
        int p = p0 + i;
        int y = p / WW;
        int x = p - y * WW;
        slab[i] = label[(size_t)b * 896 * 896 + (size_t)(4 * y) * 896 + 4 * x];
    }
    __syncthreads();

    if (mode == 0) {
        for (int i = tid; i < 1024; i += 256) atomicAdd(&cnts[slab[i]], 1.f);
    }
    for (int c = 0; c < CH; c++) {
        const float* fp = feats + ((size_t)b * CH + c) * HW + p0;
        #pragma unroll
        for (int i = tid; i < 1024; i += 256) {
            atomicAdd(&bins[slab[i] * 129 + c], fp[i]);
        }
    }
    __syncthreads();

    for (int i = tid; i < NCLS * CH; i += 256) {
        int k = i >> 7;
        int c = i & (CH - 1);
        atomicAdd(&sums[((size_t)b * NCLS + k) * CH + c], bins[k * 129 + c]);
    }
    if (mode == 0 && tid < NCLS) atomicAdd(&g_cnt[b * NCLS + tid], cnts[tid]);
}

// ---------------- RA finalize: means -> norm -> MLP -> sigmoid scales ----------------
__global__ void ra_finalize_kernel(const float* __restrict__ w1_d, const float* __restrict__ w2_d,
                                   const float* __restrict__ w1_f, const float* __restrict__ w2_f) {
    const int which = blockIdx.x & 1;
    const int b     = blockIdx.x >> 1;
    const float* sums = which ? g_sum_f : g_sum_d;
    const float* w1   = which ? w1_f : w1_d;
    const float* w2   = which ? w2_f : w2_d;

    __shared__ float att[CH];
    __shared__ float hid[8];
    const int c = threadIdx.x;  // 128 threads

    float s1 = 0.f, s2 = 0.f;
    for (int k = 0; k < NCLS; k++) {
        float cnt = g_cnt[b * NCLS + k];
        float m = sums[((size_t)b * NCLS + k) * CH + c] / fmaxf(cnt, 1.f);
        s1 += m;
        s2 += m * m;
    }
    float nrm = fmaxf(sqrtf(s2), 1e-12f);
    att[c] = s1 / nrm;
    __syncthreads();

    if (c < 8) {
        float h = 0.f;
        for (int j = 0; j < CH; j++) h += att[j] * w1[c * CH + j];
        hid[c] = fmaxf(h, 0.f);
    }
    __syncthreads();

    float o = 0.f;
    #pragma unroll
    for (int j = 0; j < 8; j++) o += hid[j] * w2[c * 8 + j];
    g_scale[(which * BATCH + b) * CH + c] = 1.f / (1.f + expf(-o));
}

// ---------------- 3x3 conv as implicit SGEMM with packed fma.rn.f32x2 ----------------
// Per block: 128 pixels x 128 output channels, K-loop over 2304 in chunks of 16.
// Thread tile 8x8 (oc x pixel); pixel pairs packed in 64-bit regs for f32x2 FMA.
__global__ __launch_bounds__(256, 2) void conv_kernel() {
    __shared__ float As[16][128];   // [kk][pixel]
    __shared__ float Bs[16][128];   // [kk][oc]

    const int tid  = threadIdx.x;
    const int b    = blockIdx.y;
    const int p0   = blockIdx.x * 128;
    const int tx   = tid & 15;    // pixel group  (8 pixels)
    const int ty   = tid >> 4;    // oc group     (8 ocs)
    const int lpix = tid & 127;   // loader: pixel / oc index
    const int lk   = tid >> 7;    // loader: k parity (0/1)

    const int p  = p0 + lpix;
    const int py = p / WW;
    const int px = p - py * WW;
    const float* __restrict__ xb = g_xcat + (size_t)b * CIN * HW;

    unsigned long long acc[8][4];
    #pragma unroll
    for (int i = 0; i < 8; i++)
        #pragma unroll
        for (int j = 0; j < 4; j++) acc[i][j] = 0ull;

    for (int k0 = 0; k0 < KTOT; k0 += 16) {
        #pragma unroll
        for (int j = 0; j < 8; j++) {
            int kk = j * 2 + lk;
            int k  = k0 + kk;
            int ci = k / 9;
            int f  = k - ci * 9;
            int fy = f / 3;
            int fx = f - fy * 3;
            int iy = py + fy - 1;
            int ix = px + fx - 1;
            float v = 0.f;
            if (iy >= 0 && iy < HH && ix >= 0 && ix < WW)
                v = xb[ci * HW + iy * WW + ix];
            As[kk][lpix] = v;
            Bs[kk][lpix] = g_wT[(k0 + kk) * CH + lpix];
        }
        __syncthreads();

        #pragma unroll
        for (int kk = 0; kk < 16; kk++) {
            ulonglong2 A0 = *reinterpret_cast<const ulonglong2*>(&As[kk][tx * 8]);
            ulonglong2 A1 = *reinterpret_cast<const ulonglong2*>(&As[kk][tx * 8 + 4]);
            unsigned long long a2[4] = {A0.x, A0.y, A1.x, A1.y};
            uint4 B0 = *reinterpret_cast<const uint4*>(&Bs[kk][ty * 8]);
            uint4 B1 = *reinterpret_cast<const uint4*>(&Bs[kk][ty * 8 + 4]);
            unsigned int bsv[8] = {B0.x, B0.y, B0.z, B0.w, B1.x, B1.y, B1.z, B1.w};
            #pragma unroll
            for (int io = 0; io < 8; io++) {
                unsigned long long b2;
                asm("mov.b64 %0, {%1, %1};" : "=l"(b2) : "r"(bsv[io]));
                #pragma unroll
                for (int ip = 0; ip < 4; ip++) {
                    asm("fma.rn.f32x2 %0, %1, %2, %0;"
                        : "+l"(acc[io][ip]) : "l"(b2), "l"(a2[ip]));
                }
            }
        }
        __syncthreads();
    }

    float* fb = g_fuse + (size_t)b * CH * HW;
    #pragma unroll
    for (int io = 0; io < 8; io++) {
        int oc = ty * 8 + io;
        float4 v0, v1;
        v0.x = __uint_as_float((unsigned)(acc[io][0]));
        v0.y = __uint_as_float((unsigned)(acc[io][0] >> 32));
        v0.z = __uint_as_float((unsigned)(acc[io][1]));
        v0.w = __uint_as_float((unsigned)(acc[io][1] >> 32));
        v1.x = __uint_as_float((unsigned)(acc[io][2]));
        v1.y = __uint_as_float((unsigned)(acc[io][2] >> 32));
        v1.z = __uint_as_float((unsigned)(acc[io][3]));
        v1.w = __uint_as_float((unsigned)(acc[io][3] >> 32));
        *reinterpret_cast<float4*>(fb + (size_t)oc * HW + p0 + tx * 8)     = v0;
        *reinterpret_cast<float4*>(fb + (size_t)oc * HW + p0 + tx * 8 + 4) = v1;
    }
}

// ---------------- final: out = fuse*scale_f + d*scale_d ----------------
__global__ void final_kernel(const float* __restrict__ dd, float* __restrict__ out) {
    int idx = blockIdx.x * 256 + threadIdx.x;
    const int n4 = BATCH * CH * HW / 4;
    if (idx >= n4) return;
    int i = idx * 4;
    int bc = i / HW;
    int b = bc >> 7;
    int c = bc & (CH - 1);
    float sd = g_scale[b * CH + c];
    float sf = g_scale[(BATCH + b) * CH + c];
    float4 dv = *reinterpret_cast<const float4*>(dd + i);
    float4 fv = *reinterpret_cast<const float4*>(g_fuse + i);
    float4 o;
    o.x = fv.x * sf + dv.x * sd;
    o.y = fv.y * sf + dv.y * sd;
    o.z = fv.z * sf + dv.z * sd;
    o.w = fv.w * sf + dv.w * sd;
    *reinterpret_cast<float4*>(out + i) = o;
}

// ---------------- launcher ----------------
extern "C" void kernel_launch(void* const* d_in, const int* in_sizes, int n_in,
                              void* d_out, int out_size) {
    const float* r      = (const float*)d_in[0];
    const float* d      = (const float*)d_in[1];
    const int*   label  = (const int*)  d_in[2];
    const float* w_fuse = (const float*)d_in[3];
    const float* w1_d   = (const float*)d_in[4];
    const float* w2_d   = (const float*)d_in[5];
    const float* w1_f   = (const float*)d_in[6];
    const float* w2_f   = (const float*)d_in[7];
    float* out = (float*)d_out;

    const int n4 = BATCH * CH * HW / 4;

    prep_kernel<<<(n4 + 255) / 256, 256>>>(r, d);
    wtrans_kernel<<<(KTOT * CH + 255) / 256, 256>>>(w_fuse);
    zero_kernel<<<(BATCH * NCLS * CH + 255) / 256, 256>>>();

    ra_stats_kernel<<<dim3(HW / 1024, BATCH), 256>>>(d, label, 0);

    conv_kernel<<<dim3(HW / 128, BATCH), 256>>>();

    ra_stats_kernel<<<dim3(HW / 1024, BATCH), 256>>>(d, label, 1);

    ra_finalize_kernel<<<2 * BATCH, CH>>>(w1_d, w2_d, w1_f, w2_f);

    final_kernel<<<(n4 + 255) / 256, 256>>>(d, out);
}